// round 3
// baseline (speedup 1.0000x reference)
#include <cuda_runtime.h>
#include <math.h>

#define BDIM 8192
#define DDIM 512
#define INV_T (1.0f/0.07f)

#define BM 128
#define BN 128
#define BK 16
#define TM 8
#define TN 8
#define NSPLIT 4
#define COLS_PER_SPLIT (BDIM/NSPLIT)          // 2048
#define NTILES_PER_SPLIT (COLS_PER_SPLIT/BN)  // 16
#define PLCAP 256                              // max same-label entries per row (class size ~82)

// ---- device scratch (no cudaMalloc allowed) ----
__device__ float  g_part_m[NSPLIT][BDIM];
__device__ float  g_part_s[NSPLIT][BDIM];
__device__ float  g_base[BDIM];
__device__ float  g_pl[BDIM * PLCAP];   // same-label logits per row
__device__ int    g_plcnt[BDIM];        // == numer_count per row
__device__ double g_acc;

// ---------------------------------------------------------------------------
__global__ void init_kernel() {
    int t = blockIdx.x * blockDim.x + threadIdx.x;
    if (t < BDIM) g_plcnt[t] = 0;
    if (t == 0) g_acc = 0.0;
}

// ---------------------------------------------------------------------------
// Fused SGEMM (C = E E^T / T) + masked online LSE per row + same-label scatter.
// grid: (NSPLIT, BDIM/BM), block: 256 threads (16x16), 8x8 per-thread tile.
__global__ __launch_bounds__(256, 2)
void lse_gemm_kernel(const float* __restrict__ E, const int* __restrict__ lab) {
    __shared__ float As[BK][BM];
    __shared__ float Bs[BK][BN];

    const int rt    = blockIdx.y;
    const int split = blockIdx.x;
    const int row0  = rt * BM;

    const int tid  = threadIdx.x;
    const int tcol = tid & 15;   // 0..15
    const int trow = tid >> 4;   // 0..15

    int rlab[TM];
#pragma unroll
    for (int i = 0; i < TM; i++) rlab[i] = lab[row0 + trow * TM + i];

    float m_run[TM], s_run[TM];
#pragma unroll
    for (int i = 0; i < TM; i++) { m_run[i] = -INFINITY; s_run[i] = 0.f; }

    // global->smem load mapping: 256 threads, each loads 2x float4 per matrix
    const int laRow = tid >> 2;        // 0..63
    const int laCol = (tid & 3) * 4;   // 0,4,8,12

    for (int ct = 0; ct < NTILES_PER_SPLIT; ct++) {
        const int col0 = split * COLS_PER_SPLIT + ct * BN;

        float acc[TM][TN];
#pragma unroll
        for (int i = 0; i < TM; i++)
#pragma unroll
            for (int j = 0; j < TN; j++) acc[i][j] = 0.f;

        for (int k0 = 0; k0 < DDIM; k0 += BK) {
#pragma unroll
            for (int h = 0; h < 2; h++) {
                const int r = laRow + h * 64;
                float4 va = *reinterpret_cast<const float4*>(&E[(size_t)(row0 + r) * DDIM + k0 + laCol]);
                As[laCol + 0][r] = va.x; As[laCol + 1][r] = va.y;
                As[laCol + 2][r] = va.z; As[laCol + 3][r] = va.w;
                float4 vb = *reinterpret_cast<const float4*>(&E[(size_t)(col0 + r) * DDIM + k0 + laCol]);
                Bs[laCol + 0][r] = vb.x; Bs[laCol + 1][r] = vb.y;
                Bs[laCol + 2][r] = vb.z; Bs[laCol + 3][r] = vb.w;
            }
            __syncthreads();
#pragma unroll
            for (int k = 0; k < BK; k++) {
                float ra[TM], rb[TN];
#pragma unroll
                for (int i = 0; i < TM; i++) ra[i] = As[k][trow * TM + i];
#pragma unroll
                for (int j = 0; j < TN; j++) rb[j] = Bs[k][tcol * TN + j];
#pragma unroll
                for (int i = 0; i < TM; i++)
#pragma unroll
                    for (int j = 0; j < TN; j++)
                        acc[i][j] = fmaf(ra[i], rb[j], acc[i][j]);
            }
            __syncthreads();
        }

        // epilogue: mask same-label, scatter same-label off-diagonal logits,
        // online LSE update (per row, across the 16 lanes sharing trow)
        int clab[TN];
#pragma unroll
        for (int j = 0; j < TN; j++) clab[j] = lab[col0 + tcol * TN + j];

#pragma unroll
        for (int i = 0; i < TM; i++) {
            const int gr = row0 + trow * TM + i;
            float l[TN];
            float lmax = -INFINITY;
#pragma unroll
            for (int j = 0; j < TN; j++) {
                float v = acc[i][j] * INV_T;
                if (clab[j] == rlab[i]) {
                    const int gc = col0 + tcol * TN + j;
                    if (gc != gr) {
                        int idx = atomicAdd(&g_plcnt[gr], 1);
                        if (idx < PLCAP) g_pl[gr * PLCAP + idx] = v;
                    }
                    l[j] = -INFINITY;
                } else {
                    l[j] = v;
                }
                lmax = fmaxf(lmax, l[j]);
            }
            // max over the 16 lanes of this row group (xor offsets stay in-half)
#pragma unroll
            for (int o = 1; o < 16; o <<= 1)
                lmax = fmaxf(lmax, __shfl_xor_sync(0xffffffffu, lmax, o));

            // sanitize so exp args are finite even in the (impossible in practice)
            // all-masked case; shuffles run unconditionally (no divergence UB)
            const float lsafe = (lmax > -INFINITY) ? lmax : 0.f;
            float ssum = 0.f;
#pragma unroll
            for (int j = 0; j < TN; j++)
                ssum += (l[j] > -INFINITY) ? __expf(l[j] - lsafe) : 0.f;
#pragma unroll
            for (int o = 1; o < 16; o <<= 1)
                ssum += __shfl_xor_sync(0xffffffffu, ssum, o);

            if (lmax > -INFINITY) {
                const float newm = fmaxf(m_run[i], lmax);
                s_run[i] = s_run[i] * __expf(m_run[i] - newm) + ssum * __expf(lmax - newm);
                m_run[i] = newm;
            }
        }
    }

    if (tcol == 0) {
#pragma unroll
        for (int i = 0; i < TM; i++) {
            const int gr = row0 + trow * TM + i;
            g_part_m[split][gr] = m_run[i];
            g_part_s[split][gr] = s_run[i];
        }
    }
}

// ---------------------------------------------------------------------------
__global__ void combine_kernel() {
    int r = blockIdx.x * blockDim.x + threadIdx.x;
    if (r >= BDIM) return;
    float M = -INFINITY;
#pragma unroll
    for (int s = 0; s < NSPLIT; s++) M = fmaxf(M, g_part_m[s][r]);
    float S = 0.f;
#pragma unroll
    for (int s = 0; s < NSPLIT; s++) S += g_part_s[s][r] * __expf(g_part_m[s][r] - M);
    g_base[r] = M + logf(S);
}

// ---------------------------------------------------------------------------
// One warp per row: sum softplus(base[i] - l) over stored same-label logits.
__global__ void pair_kernel() {
    const int warp = (blockIdx.x * blockDim.x + threadIdx.x) >> 5;
    const int lane = threadIdx.x & 31;
    if (warp >= BDIM) return;

    int cnt = g_plcnt[warp];
    if (cnt > PLCAP) cnt = PLCAP;   // defensive clamp
    const float base = g_base[warp];
    float rowsum = 0.f;
    for (int t = lane; t < cnt; t += 32) {
        const float l = g_pl[warp * PLCAP + t];
        const float x = base - l;
        // softplus(x) == logaddexp(l, base) - l, numerically stable both ways
        rowsum += (x > 0.f) ? x + log1pf(expf(-x)) : log1pf(expf(x));
    }
#pragma unroll
    for (int o = 16; o > 0; o >>= 1) rowsum += __shfl_xor_sync(0xffffffffu, rowsum, o);

    if (lane == 0 && cnt > 0)
        atomicAdd(&g_acc, (double)(rowsum / (float)cnt));
}

// ---------------------------------------------------------------------------
__global__ void finalize_kernel(float* out) {
    out[0] = (float)(g_acc / (double)BDIM);
}

// ---------------------------------------------------------------------------
extern "C" void kernel_launch(void* const* d_in, const int* in_sizes, int n_in,
                              void* d_out, int out_size) {
    // identify inputs by element count (robust to ordering):
    // embeds: 8192*512 = 4194304 f32, labels: 8192 i32
    const float* E   = nullptr;
    const int*   lab = nullptr;
    for (int i = 0; i < n_in; i++) {
        if (in_sizes[i] == BDIM * DDIM) E   = (const float*)d_in[i];
        else if (in_sizes[i] == BDIM)   lab = (const int*)d_in[i];
    }
    float* out = (float*)d_out;

    init_kernel<<<(BDIM + 255) / 256, 256>>>();
    {
        dim3 grid(NSPLIT, BDIM / BM);
        lse_gemm_kernel<<<grid, 256>>>(E, lab);
    }
    combine_kernel<<<BDIM / 256, 256>>>();
    pair_kernel<<<BDIM / 8, 256>>>();   // 1024 CTAs x 8 warps = 8192 warps, one per row
    finalize_kernel<<<1, 1>>>(out);
}

// round 4
// speedup vs baseline: 2.0614x; 2.0614x over previous
#include <cuda_runtime.h>
#include <cuda_bf16.h>
#include <math.h>
#include <stdint.h>

#define BDIM 8192
#define DDIM 512
#define INV_T (1.0f/0.07f)
#define LSE_C (1.0f/0.07f)   // static LSE shift: |e_i . e_j| <= 1 so max logit <= 1/T

#define BM 128
#define BN 128
#define KC 32
#define NKC (DDIM/KC)                 // 16
#define NSPLIT 4
#define TPS (BDIM/NSPLIT/BN)          // 16 col tiles per CTA
#define NPART (NSPLIT*4)              // 16 partials per row (4 splits x 4 N-warps)
#define PLCAP 256

#define TILE_B (BM*KC*2)              // 8192 B per bf16 tile
#define STAGE_B (4*TILE_B)            // Ahi,Alo,Bhi,Blo
#define SMEM_BYTES (2*STAGE_B + 512)  // double buffer + label tile

// ---- device scratch ----
__device__ __nv_bfloat16 g_Ehi[BDIM*DDIM];
__device__ __nv_bfloat16 g_Elo[BDIM*DDIM];
__device__ float  g_part_s[NPART][BDIM];
__device__ float  g_base[BDIM];
__device__ float  g_pl[BDIM*PLCAP];
__device__ int    g_plcnt[BDIM];
__device__ double g_acc;

// ---------------------------------------------------------------------------
__device__ __forceinline__ uint32_t pk(__nv_bfloat16 a, __nv_bfloat16 b) {
    return (uint32_t)__bfloat16_as_ushort(a) | ((uint32_t)__bfloat16_as_ushort(b) << 16);
}

__global__ void init_kernel() {
    int t = blockIdx.x * blockDim.x + threadIdx.x;
    if (t < BDIM) g_plcnt[t] = 0;
    if (t == 0) g_acc = 0.0;
}

// fp32 -> (hi, lo) bf16 split
__global__ void convert_kernel(const float* __restrict__ E) {
    int i = blockIdx.x * blockDim.x + threadIdx.x;   // over BDIM*DDIM/4
    float4 v = reinterpret_cast<const float4*>(E)[i];
    __nv_bfloat16 h0 = __float2bfloat16(v.x), h1 = __float2bfloat16(v.y);
    __nv_bfloat16 h2 = __float2bfloat16(v.z), h3 = __float2bfloat16(v.w);
    __nv_bfloat16 l0 = __float2bfloat16(v.x - __bfloat162float(h0));
    __nv_bfloat16 l1 = __float2bfloat16(v.y - __bfloat162float(h1));
    __nv_bfloat16 l2 = __float2bfloat16(v.z - __bfloat162float(h2));
    __nv_bfloat16 l3 = __float2bfloat16(v.w - __bfloat162float(h3));
    reinterpret_cast<uint2*>(g_Ehi)[i] = make_uint2(pk(h0, h1), pk(h2, h3));
    reinterpret_cast<uint2*>(g_Elo)[i] = make_uint2(pk(l0, l1), pk(l2, l3));
}

// ---------------------------------------------------------------------------
__device__ __forceinline__ void cp16(uint32_t dst, const void* src) {
    asm volatile("cp.async.cg.shared.global [%0], [%1], 16;\n" :: "r"(dst), "l"(src));
}
#define CP_COMMIT() asm volatile("cp.async.commit_group;\n" ::: "memory")
#define CP_WAIT(n)  asm volatile("cp.async.wait_group %0;\n" :: "n"(n) : "memory")

__device__ __forceinline__ void ldsm4(uint32_t& r0, uint32_t& r1, uint32_t& r2, uint32_t& r3,
                                      uint32_t addr) {
    asm volatile("ldmatrix.sync.aligned.m8n8.x4.shared.b16 {%0,%1,%2,%3}, [%4];"
                 : "=r"(r0), "=r"(r1), "=r"(r2), "=r"(r3) : "r"(addr));
}

__device__ __forceinline__ void mma_bf16(float c[4], const uint32_t a[4], uint32_t b0, uint32_t b1) {
    asm volatile(
        "mma.sync.aligned.m16n8k16.row.col.f32.bf16.bf16.f32 "
        "{%0,%1,%2,%3}, {%4,%5,%6,%7}, {%8,%9}, {%0,%1,%2,%3};"
        : "+f"(c[0]), "+f"(c[1]), "+f"(c[2]), "+f"(c[3])
        : "r"(a[0]), "r"(a[1]), "r"(a[2]), "r"(a[3]), "r"(b0), "r"(b1));
}

// ---------------------------------------------------------------------------
// Fused bf16-split HMMA GEMM (C = E E^T / T) + masked fixed-shift LSE + scatter.
// grid (NSPLIT, 64), block 256 (8 warps: 2M x 4N), warp tile 64x32.
extern __shared__ __align__(16) char dynsmem[];

__global__ void __launch_bounds__(256, 1)
lse_gemm_kernel(const int* __restrict__ lab) {
    int* labSm = (int*)(dynsmem + 2 * STAGE_B);
    const uint32_t smem_base = (uint32_t)__cvta_generic_to_shared(dynsmem);

    const int tid    = threadIdx.x;
    const int warpid = tid >> 5;
    const int lane   = tid & 31;
    const int warpM0 = (warpid >> 2) * 64;
    const int warpN0 = (warpid & 3) * 32;
    const int split  = blockIdx.x;
    const int row0   = blockIdx.y * BM;
    const int colB   = split * (BDIM / NSPLIT);

    // ldmatrix per-lane geometry
    const int li = lane & 7, lm = lane >> 3;
    const int rA    = warpM0 + li + (lm & 1) * 8;   // A fragment row (mt adds 16*mt)
    const int kAoff = lm >> 1;
    const int sA    = (rA >> 1) & 3;
    const int nB    = warpN0 + li + (lm >> 1) * 8;  // B fragment n (ntp adds 16*ntp)
    const int kBoff = lm & 1;
    const int sB    = (nB >> 1) & 3;

    int rlab[8];
#pragma unroll
    for (int mt = 0; mt < 4; mt++)
#pragma unroll
        for (int h = 0; h < 2; h++)
            rlab[mt * 2 + h] = lab[row0 + warpM0 + mt * 16 + (lane >> 2) + h * 8];

    float s_run[8];
#pragma unroll
    for (int r = 0; r < 8; r++) s_run[r] = 0.f;

    auto load_stage = [&](int stage, int col0, int kc) {
        const int ke = kc * KC;
        const uint32_t sbase = smem_base + stage * STAGE_B;
#pragma unroll
        for (int half = 0; half < 2; half++) {
            const int c = tid + half * 256;
            const int row = c >> 2, kch = c & 3;
            const uint32_t doff = (uint32_t)(row * 4 + (kch ^ ((row >> 1) & 3))) * 16;
            const size_t aoff = (size_t)(row0 + row) * DDIM + ke + kch * 8;
            const size_t boff = (size_t)(col0 + row) * DDIM + ke + kch * 8;
            cp16(sbase + 0 * TILE_B + doff, g_Ehi + aoff);
            cp16(sbase + 1 * TILE_B + doff, g_Elo + aoff);
            cp16(sbase + 2 * TILE_B + doff, g_Ehi + boff);
            cp16(sbase + 3 * TILE_B + doff, g_Elo + boff);
        }
    };

    for (int ct = 0; ct < TPS; ct++) {
        const int col0 = colB + ct * BN;

        float acc[4][4][4];
#pragma unroll
        for (int mt = 0; mt < 4; mt++)
#pragma unroll
            for (int nt = 0; nt < 4; nt++)
#pragma unroll
                for (int e = 0; e < 4; e++) acc[mt][nt][e] = 0.f;

        if (tid < 128) labSm[tid] = lab[col0 + tid];

        int buf = 0;
        load_stage(0, col0, 0);
        CP_COMMIT();

        for (int kc = 0; kc < NKC; kc++) {
            if (kc + 1 < NKC) {
                load_stage(buf ^ 1, col0, kc + 1);
                CP_COMMIT();
                CP_WAIT(1);
            } else {
                CP_WAIT(0);
            }
            __syncthreads();

            const uint32_t sbase = smem_base + buf * STAGE_B;
#pragma unroll
            for (int kk = 0; kk < 2; kk++) {
                uint32_t aHi[4][4], aLo[4][4], b[2][4];
                // A-hi fragments
#pragma unroll
                for (int mt = 0; mt < 4; mt++) {
                    uint32_t addr = sbase + 0 * TILE_B +
                        (uint32_t)(rA * 4 + mt * 64 + ((kk * 2 + kAoff) ^ sA)) * 16;
                    ldsm4(aHi[mt][0], aHi[mt][1], aHi[mt][2], aHi[mt][3], addr);
                }
                // B-hi fragments
#pragma unroll
                for (int np = 0; np < 2; np++) {
                    uint32_t addr = sbase + 2 * TILE_B +
                        (uint32_t)(nB * 4 + np * 64 + ((kk * 2 + kBoff) ^ sB)) * 16;
                    ldsm4(b[np][0], b[np][1], b[np][2], b[np][3], addr);
                }
                // hiA * hiB
#pragma unroll
                for (int mt = 0; mt < 4; mt++)
#pragma unroll
                    for (int np = 0; np < 2; np++) {
                        mma_bf16(acc[mt][2 * np + 0], aHi[mt], b[np][0], b[np][1]);
                        mma_bf16(acc[mt][2 * np + 1], aHi[mt], b[np][2], b[np][3]);
                    }
                // A-lo fragments, loA * hiB
#pragma unroll
                for (int mt = 0; mt < 4; mt++) {
                    uint32_t addr = sbase + 1 * TILE_B +
                        (uint32_t)(rA * 4 + mt * 64 + ((kk * 2 + kAoff) ^ sA)) * 16;
                    ldsm4(aLo[mt][0], aLo[mt][1], aLo[mt][2], aLo[mt][3], addr);
                }
#pragma unroll
                for (int mt = 0; mt < 4; mt++)
#pragma unroll
                    for (int np = 0; np < 2; np++) {
                        mma_bf16(acc[mt][2 * np + 0], aLo[mt], b[np][0], b[np][1]);
                        mma_bf16(acc[mt][2 * np + 1], aLo[mt], b[np][2], b[np][3]);
                    }
                // B-lo fragments, hiA * loB
#pragma unroll
                for (int np = 0; np < 2; np++) {
                    uint32_t addr = sbase + 3 * TILE_B +
                        (uint32_t)(nB * 4 + np * 64 + ((kk * 2 + kBoff) ^ sB)) * 16;
                    ldsm4(b[np][0], b[np][1], b[np][2], b[np][3], addr);
                }
#pragma unroll
                for (int mt = 0; mt < 4; mt++)
#pragma unroll
                    for (int np = 0; np < 2; np++) {
                        mma_bf16(acc[mt][2 * np + 0], aHi[mt], b[np][0], b[np][1]);
                        mma_bf16(acc[mt][2 * np + 1], aHi[mt], b[np][2], b[np][3]);
                    }
            }
            __syncthreads();
            buf ^= 1;
        }

        // ---- epilogue ----
        int clab[8];
#pragma unroll
        for (int nt = 0; nt < 4; nt++)
#pragma unroll
            for (int j = 0; j < 2; j++)
                clab[nt * 2 + j] = labSm[warpN0 + nt * 8 + (lane & 3) * 2 + j];

#pragma unroll
        for (int mt = 0; mt < 4; mt++)
#pragma unroll
            for (int h = 0; h < 2; h++) {
                const int gr = row0 + warpM0 + mt * 16 + (lane >> 2) + h * 8;
                float s = 0.f;
#pragma unroll
                for (int nt = 0; nt < 4; nt++)
#pragma unroll
                    for (int j = 0; j < 2; j++) {
                        const float v = acc[mt][nt][h * 2 + j] * INV_T;
                        if (clab[nt * 2 + j] == rlab[mt * 2 + h]) {
                            const int gc = col0 + warpN0 + nt * 8 + (lane & 3) * 2 + j;
                            if (gc != gr) {
                                int idx = atomicAdd(&g_plcnt[gr], 1);
                                if (idx < PLCAP) g_pl[gr * PLCAP + idx] = v;
                            }
                        } else {
                            s += __expf(v - LSE_C);
                        }
                    }
                s_run[mt * 2 + h] += s;
            }
        __syncthreads();  // protect labSm before next tile overwrite
    }

    // write per-(split, warpN) partial sums
#pragma unroll
    for (int r8 = 0; r8 < 8; r8++) {
        float s = s_run[r8];
        s += __shfl_xor_sync(0xffffffffu, s, 1);
        s += __shfl_xor_sync(0xffffffffu, s, 2);
        if ((lane & 3) == 0) {
            const int gr = row0 + warpM0 + (r8 >> 1) * 16 + (lane >> 2) + (r8 & 1) * 8;
            g_part_s[split * 4 + (warpid & 3)][gr] = s;
        }
    }
}

// ---------------------------------------------------------------------------
__global__ void combine_kernel() {
    int r = blockIdx.x * blockDim.x + threadIdx.x;
    if (r >= BDIM) return;
    float S = 0.f;
#pragma unroll
    for (int p = 0; p < NPART; p++) S += g_part_s[p][r];
    g_base[r] = LSE_C + logf(S);
}

// One warp per row: sum softplus(base - l) over stored same-label logits.
__global__ void pair_kernel() {
    const int warp = (blockIdx.x * blockDim.x + threadIdx.x) >> 5;
    const int lane = threadIdx.x & 31;
    if (warp >= BDIM) return;

    int cnt = g_plcnt[warp];
    if (cnt > PLCAP) cnt = PLCAP;
    const float base = g_base[warp];
    float rowsum = 0.f;
    for (int t = lane; t < cnt; t += 32) {
        const float l = g_pl[warp * PLCAP + t];
        const float x = base - l;
        rowsum += (x > 0.f) ? x + log1pf(expf(-x)) : log1pf(expf(x));
    }
#pragma unroll
    for (int o = 16; o > 0; o >>= 1) rowsum += __shfl_xor_sync(0xffffffffu, rowsum, o);

    if (lane == 0 && cnt > 0)
        atomicAdd(&g_acc, (double)(rowsum / (float)cnt));
}

__global__ void finalize_kernel(float* out) {
    out[0] = (float)(g_acc / (double)BDIM);
}

// ---------------------------------------------------------------------------
extern "C" void kernel_launch(void* const* d_in, const int* in_sizes, int n_in,
                              void* d_out, int out_size) {
    const float* E   = nullptr;
    const int*   lab = nullptr;
    for (int i = 0; i < n_in; i++) {
        if (in_sizes[i] == BDIM * DDIM) E   = (const float*)d_in[i];
        else if (in_sizes[i] == BDIM)   lab = (const int*)d_in[i];
    }
    float* out = (float*)d_out;

    cudaFuncSetAttribute(lse_gemm_kernel,
                         cudaFuncAttributeMaxDynamicSharedMemorySize, SMEM_BYTES);

    init_kernel<<<(BDIM + 255) / 256, 256>>>();
    convert_kernel<<<(BDIM * DDIM / 4) / 256, 256>>>(E);
    {
        dim3 grid(NSPLIT, BDIM / BM);
        lse_gemm_kernel<<<grid, 256, SMEM_BYTES>>>(lab);
    }
    combine_kernel<<<BDIM / 256, 256>>>();
    pair_kernel<<<BDIM / 8, 256>>>();
    finalize_kernel<<<1, 1>>>(out);
}

// round 7
// speedup vs baseline: 5.9586x; 2.8906x over previous
#include <cuda_runtime.h>
#include <cuda_bf16.h>
#include <math.h>
#include <stdint.h>

#define BDIM 8192
#define DDIM 512
#define INV_T (1.0f/0.07f)
#define LSE_C (1.0f/0.07f)

#define BM 128
#define KC 32
#define NKC (DDIM/KC)                 // 16
#define NTILE (BDIM/BM)               // 64
#define TOT_TILES (NTILE*(NTILE+1)/2) // 2080
#define PLCAP 256

#define TILE_B (BM*KC*2)              // 8192 B per bf16 tile
#define STAGE_B (4*TILE_B)            // Ahi,Alo,Bhi,Blo = 32 KB
#define SMEM_BYTES (2*STAGE_B + 1024) // double buffer + label tiles

// ---- device scratch ----
__device__ __nv_bfloat16 g_Ehi[BDIM*DDIM];
__device__ __nv_bfloat16 g_Elo[BDIM*DDIM];
__device__ float  g_rowsum[BDIM];
__device__ float  g_base[BDIM];
__device__ float  g_pl[BDIM*PLCAP];
__device__ int    g_plcnt[BDIM];
__device__ double g_acc;

// ---------------------------------------------------------------------------
__device__ __forceinline__ uint32_t pk(__nv_bfloat16 a, __nv_bfloat16 b) {
    return (uint32_t)__bfloat16_as_ushort(a) | ((uint32_t)__bfloat16_as_ushort(b) << 16);
}

__global__ void init_kernel() {
    int t = blockIdx.x * blockDim.x + threadIdx.x;
    if (t < BDIM) { g_plcnt[t] = 0; g_rowsum[t] = 0.f; }
    if (t == 0) g_acc = 0.0;
}

// fp32 -> (hi, lo) bf16 split
__global__ void convert_kernel(const float* __restrict__ E) {
    int i = blockIdx.x * blockDim.x + threadIdx.x;
    float4 v = reinterpret_cast<const float4*>(E)[i];
    __nv_bfloat16 h0 = __float2bfloat16(v.x), h1 = __float2bfloat16(v.y);
    __nv_bfloat16 h2 = __float2bfloat16(v.z), h3 = __float2bfloat16(v.w);
    __nv_bfloat16 l0 = __float2bfloat16(v.x - __bfloat162float(h0));
    __nv_bfloat16 l1 = __float2bfloat16(v.y - __bfloat162float(h1));
    __nv_bfloat16 l2 = __float2bfloat16(v.z - __bfloat162float(h2));
    __nv_bfloat16 l3 = __float2bfloat16(v.w - __bfloat162float(h3));
    reinterpret_cast<uint2*>(g_Ehi)[i] = make_uint2(pk(h0, h1), pk(h2, h3));
    reinterpret_cast<uint2*>(g_Elo)[i] = make_uint2(pk(l0, l1), pk(l2, l3));
}

// ---------------------------------------------------------------------------
__device__ __forceinline__ void cp16(uint32_t dst, const void* src) {
    asm volatile("cp.async.cg.shared.global [%0], [%1], 16;\n" :: "r"(dst), "l"(src));
}
#define CP_COMMIT() asm volatile("cp.async.commit_group;\n" ::: "memory")
#define CP_WAIT(n)  asm volatile("cp.async.wait_group %0;\n" :: "n"(n) : "memory")

__device__ __forceinline__ void ldsm4(uint32_t& r0, uint32_t& r1, uint32_t& r2, uint32_t& r3,
                                      uint32_t addr) {
    asm volatile("ldmatrix.sync.aligned.m8n8.x4.shared.b16 {%0,%1,%2,%3}, [%4];"
                 : "=r"(r0), "=r"(r1), "=r"(r2), "=r"(r3) : "r"(addr));
}

__device__ __forceinline__ void mma_bf16(float c[4], const uint32_t a[4], uint32_t b0, uint32_t b1) {
    asm volatile(
        "mma.sync.aligned.m16n8k16.row.col.f32.bf16.bf16.f32 "
        "{%0,%1,%2,%3}, {%4,%5,%6,%7}, {%8,%9}, {%0,%1,%2,%3};"
        : "+f"(c[0]), "+f"(c[1]), "+f"(c[2]), "+f"(c[3])
        : "r"(a[0]), "r"(a[1]), "r"(a[2]), "r"(a[3]), "r"(b0), "r"(b1));
}

// ---------------------------------------------------------------------------
// Symmetric-tile fused GEMM+LSE. One upper-triangle 128x128 tile per CTA.
// grid TOT_TILES, block 256 (8 warps: 2M x 4N), warp tile 64x32.
extern __shared__ __align__(16) char dynsmem[];

__global__ void __launch_bounds__(256, 2)
lse_gemm_kernel(const int* __restrict__ lab) {
    int* labA = (int*)(dynsmem + 2 * STAGE_B);
    int* labB = labA + 128;
    const uint32_t smem_base = (uint32_t)__cvta_generic_to_shared(dynsmem);

    // decode upper-triangle tile (I, J), J >= I
    int I = 0, rem = blockIdx.x;
    while (rem >= (NTILE - I)) { rem -= (NTILE - I); I++; }
    const int J = I + rem;
    const int row0 = I * BM;
    const int col0 = J * BM;
    const bool offdiag = (I != J);

    const int tid    = threadIdx.x;
    const int warpid = tid >> 5;
    const int lane   = tid & 31;
    const int warpM0 = (warpid >> 2) * 64;
    const int warpN0 = (warpid & 3) * 32;

    // ldmatrix per-lane geometry (identical to R4, verified rel_err 0)
    const int li = lane & 7, lm = lane >> 3;
    const int rA    = warpM0 + li + (lm & 1) * 8;
    const int kAoff = lm >> 1;
    const int sA    = (rA >> 1) & 3;
    const int nB    = warpN0 + li + (lm >> 1) * 8;
    const int kBoff = lm & 1;
    const int sB    = (nB >> 1) & 3;

    if (tid < 128) labA[tid] = lab[row0 + tid];
    else           labB[tid - 128] = lab[col0 + tid - 128];

    // global->smem load mapping
    const int laRow = tid >> 2;        // reused twice (rows 0..63, 64..127)
    (void)laRow;

    float acc[4][4][4];
#pragma unroll
    for (int mt = 0; mt < 4; mt++)
#pragma unroll
        for (int nt = 0; nt < 4; nt++)
#pragma unroll
            for (int e = 0; e < 4; e++) acc[mt][nt][e] = 0.f;

    auto load_stage = [&](int stage, int kc) {
        const int ke = kc * KC;
        const uint32_t sbase = smem_base + stage * STAGE_B;
#pragma unroll
        for (int half = 0; half < 2; half++) {
            const int c = tid + half * 256;
            const int row = c >> 2, kch = c & 3;
            const uint32_t doff = (uint32_t)(row * 4 + (kch ^ ((row >> 1) & 3))) * 16;
            const size_t aoff = (size_t)(row0 + row) * DDIM + ke + kch * 8;
            const size_t boff = (size_t)(col0 + row) * DDIM + ke + kch * 8;
            cp16(sbase + 0 * TILE_B + doff, g_Ehi + aoff);
            cp16(sbase + 1 * TILE_B + doff, g_Elo + aoff);
            cp16(sbase + 2 * TILE_B + doff, g_Ehi + boff);
            cp16(sbase + 3 * TILE_B + doff, g_Elo + boff);
        }
    };

    int buf = 0;
    load_stage(0, 0);
    CP_COMMIT();

    for (int kc = 0; kc < NKC; kc++) {
        if (kc + 1 < NKC) {
            load_stage(buf ^ 1, kc + 1);
            CP_COMMIT();
            CP_WAIT(1);
        } else {
            CP_WAIT(0);
        }
        __syncthreads();

        const uint32_t sbase = smem_base + buf * STAGE_B;
#pragma unroll
        for (int kk = 0; kk < 2; kk++) {
            uint32_t aHi[4][4], aLo[4][4], b[2][4];
#pragma unroll
            for (int mt = 0; mt < 4; mt++) {
                uint32_t addr = sbase + 0 * TILE_B +
                    (uint32_t)(rA * 4 + mt * 64 + ((kk * 2 + kAoff) ^ sA)) * 16;
                ldsm4(aHi[mt][0], aHi[mt][1], aHi[mt][2], aHi[mt][3], addr);
            }
#pragma unroll
            for (int np = 0; np < 2; np++) {
                uint32_t addr = sbase + 2 * TILE_B +
                    (uint32_t)(nB * 4 + np * 64 + ((kk * 2 + kBoff) ^ sB)) * 16;
                ldsm4(b[np][0], b[np][1], b[np][2], b[np][3], addr);
            }
#pragma unroll
            for (int mt = 0; mt < 4; mt++)
#pragma unroll
                for (int np = 0; np < 2; np++) {
                    mma_bf16(acc[mt][2 * np + 0], aHi[mt], b[np][0], b[np][1]);
                    mma_bf16(acc[mt][2 * np + 1], aHi[mt], b[np][2], b[np][3]);
                }
#pragma unroll
            for (int mt = 0; mt < 4; mt++) {
                uint32_t addr = sbase + 1 * TILE_B +
                    (uint32_t)(rA * 4 + mt * 64 + ((kk * 2 + kAoff) ^ sA)) * 16;
                ldsm4(aLo[mt][0], aLo[mt][1], aLo[mt][2], aLo[mt][3], addr);
            }
#pragma unroll
            for (int mt = 0; mt < 4; mt++)
#pragma unroll
                for (int np = 0; np < 2; np++) {
                    mma_bf16(acc[mt][2 * np + 0], aLo[mt], b[np][0], b[np][1]);
                    mma_bf16(acc[mt][2 * np + 1], aLo[mt], b[np][2], b[np][3]);
                }
#pragma unroll
            for (int np = 0; np < 2; np++) {
                uint32_t addr = sbase + 3 * TILE_B +
                    (uint32_t)(nB * 4 + np * 64 + ((kk * 2 + kBoff) ^ sB)) * 16;
                ldsm4(b[np][0], b[np][1], b[np][2], b[np][3], addr);
            }
#pragma unroll
            for (int mt = 0; mt < 4; mt++)
#pragma unroll
                for (int np = 0; np < 2; np++) {
                    mma_bf16(acc[mt][2 * np + 0], aHi[mt], b[np][0], b[np][1]);
                    mma_bf16(acc[mt][2 * np + 1], aHi[mt], b[np][2], b[np][3]);
                }
        }
        __syncthreads();
        buf ^= 1;
    }

    // ---- epilogue: row sums + (off-diag) column sums + same-label scatter ----
    int rlab[8], clab[8];
#pragma unroll
    for (int mt = 0; mt < 4; mt++)
#pragma unroll
        for (int h = 0; h < 2; h++)
            rlab[mt * 2 + h] = labA[warpM0 + mt * 16 + (lane >> 2) + h * 8];
#pragma unroll
    for (int nt = 0; nt < 4; nt++)
#pragma unroll
        for (int j = 0; j < 2; j++)
            clab[nt * 2 + j] = labB[warpN0 + nt * 8 + (lane & 3) * 2 + j];

    float colAcc[8];
#pragma unroll
    for (int i = 0; i < 8; i++) colAcc[i] = 0.f;

#pragma unroll
    for (int mt = 0; mt < 4; mt++)
#pragma unroll
        for (int h = 0; h < 2; h++) {
            const int gr = row0 + warpM0 + mt * 16 + (lane >> 2) + h * 8;
            float s = 0.f;
#pragma unroll
            for (int nt = 0; nt < 4; nt++)
#pragma unroll
                for (int j = 0; j < 2; j++) {
                    const float v = acc[mt][nt][h * 2 + j] * INV_T;
                    const int gc = col0 + warpN0 + nt * 8 + (lane & 3) * 2 + j;
                    if (clab[nt * 2 + j] == rlab[mt * 2 + h]) {
                        if (gc != gr) {
                            int idx = atomicAdd(&g_plcnt[gr], 1);
                            if (idx < PLCAP) g_pl[gr * PLCAP + idx] = v;
                            if (offdiag) {
                                int idc = atomicAdd(&g_plcnt[gc], 1);
                                if (idc < PLCAP) g_pl[gc * PLCAP + idc] = v;
                            }
                        }
                    } else {
                        const float e = __expf(v - LSE_C);
                        s += e;
                        colAcc[nt * 2 + j] += e;
                    }
                }
            // reduce row sum across the 4 lanes of the quad
            s += __shfl_xor_sync(0xffffffffu, s, 1);
            s += __shfl_xor_sync(0xffffffffu, s, 2);
            if ((lane & 3) == 0) atomicAdd(&g_rowsum[gr], s);
        }

    if (offdiag) {
        // column sums: reduce across lane>>2 (xor 4,8,16), lanes 0-3 hold totals
#pragma unroll
        for (int idx = 0; idx < 8; idx++) {
            float cs = colAcc[idx];
            cs += __shfl_xor_sync(0xffffffffu, cs, 4);
            cs += __shfl_xor_sync(0xffffffffu, cs, 8);
            cs += __shfl_xor_sync(0xffffffffu, cs, 16);
            if ((lane >> 2) == 0) {
                const int gc = col0 + warpN0 + (idx >> 1) * 8 + (lane & 3) * 2 + (idx & 1);
                atomicAdd(&g_rowsum[gc], cs);
            }
        }
    }
}

// ---------------------------------------------------------------------------
__global__ void combine_kernel() {
    int r = blockIdx.x * blockDim.x + threadIdx.x;
    if (r >= BDIM) return;
    g_base[r] = LSE_C + logf(g_rowsum[r]);
}

// One warp per row: sum softplus(base - l) over stored same-label logits.
__global__ void pair_kernel() {
    const int warp = (blockIdx.x * blockDim.x + threadIdx.x) >> 5;
    const int lane = threadIdx.x & 31;
    if (warp >= BDIM) return;
    int cnt = g_plcnt[warp];
    if (cnt > PLCAP) cnt = PLCAP;
    const float base = g_base[warp];
    float rowsum = 0.f;
    for (int t = lane; t < cnt; t += 32) {
        const float l = g_pl[warp * PLCAP + t];
        const float x = base - l;
        rowsum += (x > 0.f) ? x + log1pf(expf(-x)) : log1pf(expf(x));
    }
#pragma unroll
    for (int o = 16; o > 0; o >>= 1) rowsum += __shfl_xor_sync(0xffffffffu, rowsum, o);
    if (lane == 0 && cnt > 0)
        atomicAdd(&g_acc, (double)(rowsum / (float)cnt));
}

__global__ void finalize_kernel(float* out) {
    out[0] = (float)(g_acc / (double)BDIM);
}

// ---------------------------------------------------------------------------
extern "C" void kernel_launch(void* const* d_in, const int* in_sizes, int n_in,
                              void* d_out, int out_size) {
    const float* E   = nullptr;
    const int*   lab = nullptr;
    for (int i = 0; i < n_in; i++) {
        if (in_sizes[i] == BDIM * DDIM) E   = (const float*)d_in[i];
        else if (in_sizes[i] == BDIM)   lab = (const int*)d_in[i];
    }
    float* out = (float*)d_out;

    cudaFuncSetAttribute(lse_gemm_kernel,
                         cudaFuncAttributeMaxDynamicSharedMemorySize, SMEM_BYTES);

    init_kernel<<<(BDIM + 255) / 256, 256>>>();
    convert_kernel<<<(BDIM * DDIM / 4) / 256, 256>>>(E);
    lse_gemm_kernel<<<TOT_TILES, 256, SMEM_BYTES>>>(lab);
    combine_kernel<<<BDIM / 256, 256>>>();
    pair_kernel<<<BDIM / 8, 256>>>();
    finalize_kernel<<<1, 1>>>(out);
}

// round 9
// speedup vs baseline: 8.9281x; 1.4983x over previous
#include <cuda_runtime.h>
#include <cuda_fp16.h>
#include <math.h>
#include <stdint.h>

#define BDIM 8192
#define DDIM 512
#define INV_T (1.0f/0.07f)
#define LSE_C (1.0f/0.07f)

#define BM 128
#define KC 32
#define NKC (DDIM/KC)                 // 16
#define NTILE (BDIM/BM)               // 64
#define TOT_TILES (NTILE*(NTILE+1)/2) // 2080
#define PLCAP 256

#define TILE_B (BM*KC*2)              // 8192 B per fp16 tile
#define STAGE_B (2*TILE_B)            // A, B = 16 KB
#define SMEM_BYTES (2*STAGE_B + 1024) // double buffer + label tiles

// ---- device scratch ----
__device__ __half g_Eh[BDIM*DDIM];
__device__ float  g_rowsum[BDIM];
__device__ float  g_pl[BDIM*PLCAP];
__device__ int    g_plcnt[BDIM];
__device__ double g_acc;

// ---------------------------------------------------------------------------
__global__ void init_kernel() {
    int t = blockIdx.x * blockDim.x + threadIdx.x;
    if (t < BDIM) { g_plcnt[t] = 0; g_rowsum[t] = 0.f; }
    if (t == 0) g_acc = 0.0;
}

// fp32 -> fp16
__global__ void convert_kernel(const float* __restrict__ E) {
    int i = blockIdx.x * blockDim.x + threadIdx.x;   // over BDIM*DDIM/4
    float4 v = reinterpret_cast<const float4*>(E)[i];
    __half2* dst = reinterpret_cast<__half2*>(g_Eh) + 2 * i;
    dst[0] = __floats2half2_rn(v.x, v.y);
    dst[1] = __floats2half2_rn(v.z, v.w);
}

// ---------------------------------------------------------------------------
__device__ __forceinline__ void cp16(uint32_t dst, const void* src) {
    asm volatile("cp.async.cg.shared.global [%0], [%1], 16;\n" :: "r"(dst), "l"(src));
}
#define CP_COMMIT() asm volatile("cp.async.commit_group;\n" ::: "memory")
#define CP_WAIT(n)  asm volatile("cp.async.wait_group %0;\n" :: "n"(n) : "memory")

__device__ __forceinline__ void ldsm4(uint32_t& r0, uint32_t& r1, uint32_t& r2, uint32_t& r3,
                                      uint32_t addr) {
    asm volatile("ldmatrix.sync.aligned.m8n8.x4.shared.b16 {%0,%1,%2,%3}, [%4];"
                 : "=r"(r0), "=r"(r1), "=r"(r2), "=r"(r3) : "r"(addr));
}

__device__ __forceinline__ void mma_f16(float c[4], const uint32_t a[4], uint32_t b0, uint32_t b1) {
    asm volatile(
        "mma.sync.aligned.m16n8k16.row.col.f32.f16.f16.f32 "
        "{%0,%1,%2,%3}, {%4,%5,%6,%7}, {%8,%9}, {%0,%1,%2,%3};"
        : "+f"(c[0]), "+f"(c[1]), "+f"(c[2]), "+f"(c[3])
        : "r"(a[0]), "r"(a[1]), "r"(a[2]), "r"(a[3]), "r"(b0), "r"(b1));
}

// ---------------------------------------------------------------------------
// Symmetric-tile fused GEMM+LSE. One upper-triangle 128x128 tile per CTA.
// grid TOT_TILES, block 256 (8 warps: 2M x 4N), warp tile 64x32.
extern __shared__ __align__(16) char dynsmem[];

__global__ void __launch_bounds__(256, 2)
lse_gemm_kernel(const int* __restrict__ lab) {
    int* labA = (int*)(dynsmem + 2 * STAGE_B);
    int* labB = labA + 128;
    const uint32_t smem_base = (uint32_t)__cvta_generic_to_shared(dynsmem);

    // decode upper-triangle tile (I, J), J >= I
    int I = 0, rem = blockIdx.x;
    while (rem >= (NTILE - I)) { rem -= (NTILE - I); I++; }
    const int J = I + rem;
    const int row0 = I * BM;
    const int col0 = J * BM;
    const bool offdiag = (I != J);

    const int tid    = threadIdx.x;
    const int warpid = tid >> 5;
    const int lane   = tid & 31;
    const int warpM0 = (warpid >> 2) * 64;
    const int warpN0 = (warpid & 3) * 32;

    // ldmatrix per-lane geometry (verified in R4/R7, rel_err 0)
    const int li = lane & 7, lm = lane >> 3;
    const int rA    = warpM0 + li + (lm & 1) * 8;
    const int kAoff = lm >> 1;
    const int sA    = (rA >> 1) & 3;
    const int nB    = warpN0 + li + (lm >> 1) * 8;
    const int kBoff = lm & 1;
    const int sB    = (nB >> 1) & 3;

    if (tid < 128) labA[tid] = lab[row0 + tid];
    else           labB[tid - 128] = lab[col0 + tid - 128];

    float acc[4][4][4];
#pragma unroll
    for (int mt = 0; mt < 4; mt++)
#pragma unroll
        for (int nt = 0; nt < 4; nt++)
#pragma unroll
            for (int e = 0; e < 4; e++) acc[mt][nt][e] = 0.f;

    auto load_stage = [&](int stage, int kc) {
        const int ke = kc * KC;
        const uint32_t sbase = smem_base + stage * STAGE_B;
#pragma unroll
        for (int half = 0; half < 2; half++) {
            const int c = tid + half * 256;
            const int row = c >> 2, kch = c & 3;
            const uint32_t doff = (uint32_t)(row * 4 + (kch ^ ((row >> 1) & 3))) * 16;
            const size_t aoff = (size_t)(row0 + row) * DDIM + ke + kch * 8;
            const size_t boff = (size_t)(col0 + row) * DDIM + ke + kch * 8;
            cp16(sbase + 0 * TILE_B + doff, g_Eh + aoff);
            cp16(sbase + 1 * TILE_B + doff, g_Eh + boff);
        }
    };

    int buf = 0;
    load_stage(0, 0);
    CP_COMMIT();

    for (int kc = 0; kc < NKC; kc++) {
        if (kc + 1 < NKC) {
            load_stage(buf ^ 1, kc + 1);
            CP_COMMIT();
            CP_WAIT(1);
        } else {
            CP_WAIT(0);
        }
        __syncthreads();

        const uint32_t sbase = smem_base + buf * STAGE_B;
#pragma unroll
        for (int kk = 0; kk < 2; kk++) {
            uint32_t a[4][4], b[2][4];
#pragma unroll
            for (int mt = 0; mt < 4; mt++) {
                uint32_t addr = sbase + 0 * TILE_B +
                    (uint32_t)(rA * 4 + mt * 64 + ((kk * 2 + kAoff) ^ sA)) * 16;
                ldsm4(a[mt][0], a[mt][1], a[mt][2], a[mt][3], addr);
            }
#pragma unroll
            for (int np = 0; np < 2; np++) {
                uint32_t addr = sbase + 1 * TILE_B +
                    (uint32_t)(nB * 4 + np * 64 + ((kk * 2 + kBoff) ^ sB)) * 16;
                ldsm4(b[np][0], b[np][1], b[np][2], b[np][3], addr);
            }
#pragma unroll
            for (int mt = 0; mt < 4; mt++)
#pragma unroll
                for (int np = 0; np < 2; np++) {
                    mma_f16(acc[mt][2 * np + 0], a[mt], b[np][0], b[np][1]);
                    mma_f16(acc[mt][2 * np + 1], a[mt], b[np][2], b[np][3]);
                }
        }
        __syncthreads();
        buf ^= 1;
    }

    // ---- epilogue: row sums + (off-diag) column sums + same-label scatter ----
    int rlab[8], clab[8];
#pragma unroll
    for (int mt = 0; mt < 4; mt++)
#pragma unroll
        for (int h = 0; h < 2; h++)
            rlab[mt * 2 + h] = labA[warpM0 + mt * 16 + (lane >> 2) + h * 8];
#pragma unroll
    for (int nt = 0; nt < 4; nt++)
#pragma unroll
        for (int j = 0; j < 2; j++)
            clab[nt * 2 + j] = labB[warpN0 + nt * 8 + (lane & 3) * 2 + j];

    float colAcc[8];
#pragma unroll
    for (int i = 0; i < 8; i++) colAcc[i] = 0.f;

#pragma unroll
    for (int mt = 0; mt < 4; mt++)
#pragma unroll
        for (int h = 0; h < 2; h++) {
            const int gr = row0 + warpM0 + mt * 16 + (lane >> 2) + h * 8;
            float s = 0.f;
#pragma unroll
            for (int nt = 0; nt < 4; nt++)
#pragma unroll
                for (int j = 0; j < 2; j++) {
                    const float v = acc[mt][nt][h * 2 + j] * INV_T;
                    const int gc = col0 + warpN0 + nt * 8 + (lane & 3) * 2 + j;
                    if (clab[nt * 2 + j] == rlab[mt * 2 + h]) {
                        if (gc != gr) {
                            int idx = atomicAdd(&g_plcnt[gr], 1);
                            if (idx < PLCAP) g_pl[gr * PLCAP + idx] = v;
                            if (offdiag) {
                                int idc = atomicAdd(&g_plcnt[gc], 1);
                                if (idc < PLCAP) g_pl[gc * PLCAP + idc] = v;
                            }
                        }
                    } else {
                        const float e = __expf(v - LSE_C);
                        s += e;
                        colAcc[nt * 2 + j] += e;
                    }
                }
            // reduce row sum across the 4 lanes of the quad
            s += __shfl_xor_sync(0xffffffffu, s, 1);
            s += __shfl_xor_sync(0xffffffffu, s, 2);
            if ((lane & 3) == 0) atomicAdd(&g_rowsum[gr], s);
        }

    if (offdiag) {
        // column sums: reduce across lane>>2 (xor 4,8,16), lanes 0-3 hold totals
#pragma unroll
        for (int idx = 0; idx < 8; idx++) {
            float cs = colAcc[idx];
            cs += __shfl_xor_sync(0xffffffffu, cs, 4);
            cs += __shfl_xor_sync(0xffffffffu, cs, 8);
            cs += __shfl_xor_sync(0xffffffffu, cs, 16);
            if ((lane >> 2) == 0) {
                const int gc = col0 + warpN0 + (idx >> 1) * 8 + (lane & 3) * 2 + (idx & 1);
                atomicAdd(&g_rowsum[gc], cs);
            }
        }
    }
}

// ---------------------------------------------------------------------------
// One warp per row: base = LSE_C + log(rowsum); sum softplus(base - l).
__global__ void pair_kernel() {
    const int warp = (blockIdx.x * blockDim.x + threadIdx.x) >> 5;
    const int lane = threadIdx.x & 31;
    if (warp >= BDIM) return;
    int cnt = g_plcnt[warp];
    if (cnt > PLCAP) cnt = PLCAP;
    const float base = LSE_C + logf(g_rowsum[warp]);
    float rowsum = 0.f;
    for (int t = lane; t < cnt; t += 32) {
        const float l = g_pl[warp * PLCAP + t];
        const float x = base - l;
        rowsum += (x > 0.f) ? x + log1pf(expf(-x)) : log1pf(expf(x));
    }
#pragma unroll
    for (int o = 16; o > 0; o >>= 1) rowsum += __shfl_xor_sync(0xffffffffu, rowsum, o);
    if (lane == 0 && cnt > 0)
        atomicAdd(&g_acc, (double)(rowsum / (float)cnt));
}

__global__ void finalize_kernel(float* out) {
    out[0] = (float)(g_acc / (double)BDIM);
}

// ---------------------------------------------------------------------------
extern "C" void kernel_launch(void* const* d_in, const int* in_sizes, int n_in,
                              void* d_out, int out_size) {
    const float* E   = nullptr;
    const int*   lab = nullptr;
    for (int i = 0; i < n_in; i++) {
        if (in_sizes[i] == BDIM * DDIM) E   = (const float*)d_in[i];
        else if (in_sizes[i] == BDIM)   lab = (const int*)d_in[i];
    }
    float* out = (float*)d_out;

    cudaFuncSetAttribute(lse_gemm_kernel,
                         cudaFuncAttributeMaxDynamicSharedMemorySize, SMEM_BYTES);

    init_kernel<<<(BDIM + 255) / 256, 256>>>();
    convert_kernel<<<(BDIM * DDIM / 4) / 256, 256>>>(E);
    lse_gemm_kernel<<<TOT_TILES, 256, SMEM_BYTES>>>(lab);
    pair_kernel<<<BDIM / 8, 256>>>();
    finalize_kernel<<<1, 1>>>(out);
}

// round 10
// speedup vs baseline: 9.4127x; 1.0543x over previous
#include <cuda_runtime.h>
#include <cuda_fp16.h>
#include <math.h>
#include <stdint.h>

#define BDIM 8192
#define DDIM 512
#define INV_T (1.0f/0.07f)
#define LSE_C (1.0f/0.07f)

#define BM 128
#define KC 64
#define NKC (DDIM/KC)                 // 8
#define NTILE (BDIM/BM)               // 64
#define TOT_TILES (NTILE*(NTILE+1)/2) // 2080
#define PLCAP 256
#define NSTAGE 3

#define TILE_B (BM*KC*2)              // 16384 B per fp16 tile (128 B/row)
#define STAGE_B (2*TILE_B)            // A + B = 32 KB
#define SMEM_BYTES (NSTAGE*STAGE_B + 1024)

// ---- device scratch ----
__device__ __half g_Eh[BDIM*DDIM];
__device__ float  g_rowsum[BDIM];
__device__ float  g_pl[BDIM*PLCAP];
__device__ int    g_plcnt[BDIM];
__device__ double g_acc;

// ---------------------------------------------------------------------------
__global__ void init_kernel() {
    int t = blockIdx.x * blockDim.x + threadIdx.x;
    if (t < BDIM) { g_plcnt[t] = 0; g_rowsum[t] = 0.f; }
    if (t == 0) g_acc = 0.0;
}

// fp32 -> fp16
__global__ void convert_kernel(const float* __restrict__ E) {
    int i = blockIdx.x * blockDim.x + threadIdx.x;   // over BDIM*DDIM/4
    float4 v = reinterpret_cast<const float4*>(E)[i];
    __half2* dst = reinterpret_cast<__half2*>(g_Eh) + 2 * i;
    dst[0] = __floats2half2_rn(v.x, v.y);
    dst[1] = __floats2half2_rn(v.z, v.w);
}

// ---------------------------------------------------------------------------
__device__ __forceinline__ void cp16(uint32_t dst, const void* src) {
    asm volatile("cp.async.cg.shared.global [%0], [%1], 16;\n" :: "r"(dst), "l"(src));
}
#define CP_COMMIT() asm volatile("cp.async.commit_group;\n" ::: "memory")
#define CP_WAIT(n)  asm volatile("cp.async.wait_group %0;\n" :: "n"(n) : "memory")

__device__ __forceinline__ void ldsm4(uint32_t& r0, uint32_t& r1, uint32_t& r2, uint32_t& r3,
                                      uint32_t addr) {
    asm volatile("ldmatrix.sync.aligned.m8n8.x4.shared.b16 {%0,%1,%2,%3}, [%4];"
                 : "=r"(r0), "=r"(r1), "=r"(r2), "=r"(r3) : "r"(addr));
}

__device__ __forceinline__ void mma_f16(float c[4], const uint32_t a[4], uint32_t b0, uint32_t b1) {
    asm volatile(
        "mma.sync.aligned.m16n8k16.row.col.f32.f16.f16.f32 "
        "{%0,%1,%2,%3}, {%4,%5,%6,%7}, {%8,%9}, {%0,%1,%2,%3};"
        : "+f"(c[0]), "+f"(c[1]), "+f"(c[2]), "+f"(c[3])
        : "r"(a[0]), "r"(a[1]), "r"(a[2]), "r"(a[3]), "r"(b0), "r"(b1));
}

// ---------------------------------------------------------------------------
// Symmetric-tile fused GEMM+LSE. One upper-triangle 128x128 tile per CTA.
// grid TOT_TILES, block 256 (8 warps: 2M x 4N), warp tile 64x32.
// 3-stage cp.async ring, KC=64, one __syncthreads per k-chunk.
extern __shared__ __align__(16) char dynsmem[];

__global__ void __launch_bounds__(256, 2)
lse_gemm_kernel(const int* __restrict__ lab) {
    int* labA = (int*)(dynsmem + NSTAGE * STAGE_B);
    int* labB = labA + 128;
    const uint32_t smem_base = (uint32_t)__cvta_generic_to_shared(dynsmem);

    // decode upper-triangle tile (I, J), J >= I
    int I = 0, rem = blockIdx.x;
    while (rem >= (NTILE - I)) { rem -= (NTILE - I); I++; }
    const int J = I + rem;
    const int row0 = I * BM;
    const int col0 = J * BM;
    const bool offdiag = (I != J);

    const int tid    = threadIdx.x;
    const int warpid = tid >> 5;
    const int lane   = tid & 31;
    const int warpM0 = (warpid >> 2) * 64;
    const int warpN0 = (warpid & 3) * 32;

    // ldmatrix per-lane geometry (lane mapping verified in R4/R7/R9)
    const int li = lane & 7, lm = lane >> 3;
    const int rA    = warpM0 + li + (lm & 1) * 8;
    const int kAoff = lm >> 1;
    const int nB    = warpN0 + li + (lm >> 1) * 8;
    const int kBoff = lm & 1;
    const int sA    = li;   // (row & 7) for SW128, mt*16 offsets preserve low 3 bits
    const int sB    = li;

    if (tid < 128) labA[tid] = lab[row0 + tid];
    else           labB[tid - 128] = lab[col0 + tid - 128];

    float acc[4][4][4];
#pragma unroll
    for (int mt = 0; mt < 4; mt++)
#pragma unroll
        for (int nt = 0; nt < 4; nt++)
#pragma unroll
            for (int e = 0; e < 4; e++) acc[mt][nt][e] = 0.f;

    // each thread: 4 cp16 for A + 4 cp16 for B per stage (1024 chunks each)
    auto load_stage = [&](int stage, int kc) {
        const int ke = kc * KC;
        const uint32_t sbase = smem_base + stage * STAGE_B;
#pragma unroll
        for (int half = 0; half < 4; half++) {
            const int c = tid + half * 256;          // 0..1023
            const int row = c >> 3, chk = c & 7;
            const uint32_t doff = (uint32_t)(row * 8 + (chk ^ (row & 7))) * 16;
            const size_t aoff = (size_t)(row0 + row) * DDIM + ke + chk * 8;
            const size_t boff = (size_t)(col0 + row) * DDIM + ke + chk * 8;
            cp16(sbase + 0 * TILE_B + doff, g_Eh + aoff);
            cp16(sbase + 1 * TILE_B + doff, g_Eh + boff);
        }
        CP_COMMIT();
    };

    // prologue: stages 0,1 in flight
    load_stage(0, 0);
    load_stage(1, 1);

    int stage = 0;
    for (int kc = 0; kc < NKC; kc++) {
        if (kc + 1 < NKC) { CP_WAIT(1); } else { CP_WAIT(0); }
        __syncthreads();            // stage `stage` ready; all warps done with stage (kc-1)%3

        if (kc + 2 < NKC) {
            int ns = stage + 2; if (ns >= NSTAGE) ns -= NSTAGE;
            load_stage(ns, kc + 2);
        }

        const uint32_t sbase = smem_base + stage * STAGE_B;
#pragma unroll
        for (int kk = 0; kk < 4; kk++) {
            uint32_t a[4][4], b[2][4];
#pragma unroll
            for (int mt = 0; mt < 4; mt++) {
                uint32_t addr = sbase + 0 * TILE_B +
                    (uint32_t)((rA + mt * 16) * 8 + ((kk * 2 + kAoff) ^ sA)) * 16;
                ldsm4(a[mt][0], a[mt][1], a[mt][2], a[mt][3], addr);
            }
#pragma unroll
            for (int np = 0; np < 2; np++) {
                uint32_t addr = sbase + 1 * TILE_B +
                    (uint32_t)((nB + np * 16) * 8 + ((kk * 2 + kBoff) ^ sB)) * 16;
                ldsm4(b[np][0], b[np][1], b[np][2], b[np][3], addr);
            }
#pragma unroll
            for (int mt = 0; mt < 4; mt++)
#pragma unroll
                for (int np = 0; np < 2; np++) {
                    mma_f16(acc[mt][2 * np + 0], a[mt], b[np][0], b[np][1]);
                    mma_f16(acc[mt][2 * np + 1], a[mt], b[np][2], b[np][3]);
                }
        }
        if (++stage >= NSTAGE) stage -= NSTAGE;
    }
    __syncthreads();   // all compute done before epilogue (labels reused below)

    // ---- epilogue: row sums + (off-diag) column sums + same-label scatter ----
    int rlab[8], clab[8];
#pragma unroll
    for (int mt = 0; mt < 4; mt++)
#pragma unroll
        for (int h = 0; h < 2; h++)
            rlab[mt * 2 + h] = labA[warpM0 + mt * 16 + (lane >> 2) + h * 8];
#pragma unroll
    for (int nt = 0; nt < 4; nt++)
#pragma unroll
        for (int j = 0; j < 2; j++)
            clab[nt * 2 + j] = labB[warpN0 + nt * 8 + (lane & 3) * 2 + j];

    float colAcc[8];
#pragma unroll
    for (int i = 0; i < 8; i++) colAcc[i] = 0.f;

#pragma unroll
    for (int mt = 0; mt < 4; mt++)
#pragma unroll
        for (int h = 0; h < 2; h++) {
            const int gr = row0 + warpM0 + mt * 16 + (lane >> 2) + h * 8;
            float s = 0.f;
#pragma unroll
            for (int nt = 0; nt < 4; nt++)
#pragma unroll
                for (int j = 0; j < 2; j++) {
                    const float v = acc[mt][nt][h * 2 + j] * INV_T;
                    const int gc = col0 + warpN0 + nt * 8 + (lane & 3) * 2 + j;
                    if (clab[nt * 2 + j] == rlab[mt * 2 + h]) {
                        if (gc != gr) {
                            int idx = atomicAdd(&g_plcnt[gr], 1);
                            if (idx < PLCAP) g_pl[gr * PLCAP + idx] = v;
                            if (offdiag) {
                                int idc = atomicAdd(&g_plcnt[gc], 1);
                                if (idc < PLCAP) g_pl[gc * PLCAP + idc] = v;
                            }
                        }
                    } else {
                        const float e = __expf(v - LSE_C);
                        s += e;
                        colAcc[nt * 2 + j] += e;
                    }
                }
            // reduce row sum across the 4 lanes of the quad
            s += __shfl_xor_sync(0xffffffffu, s, 1);
            s += __shfl_xor_sync(0xffffffffu, s, 2);
            if ((lane & 3) == 0) atomicAdd(&g_rowsum[gr], s);
        }

    if (offdiag) {
        // column sums: reduce across lane>>2 (xor 4,8,16), lanes 0-3 hold totals
#pragma unroll
        for (int idx = 0; idx < 8; idx++) {
            float cs = colAcc[idx];
            cs += __shfl_xor_sync(0xffffffffu, cs, 4);
            cs += __shfl_xor_sync(0xffffffffu, cs, 8);
            cs += __shfl_xor_sync(0xffffffffu, cs, 16);
            if ((lane >> 2) == 0) {
                const int gc = col0 + warpN0 + (idx >> 1) * 8 + (lane & 3) * 2 + (idx & 1);
                atomicAdd(&g_rowsum[gc], cs);
            }
        }
    }
}

// ---------------------------------------------------------------------------
// One warp per row: base = LSE_C + log(rowsum); sum softplus(base - l).
__global__ void pair_kernel() {
    const int warp = (blockIdx.x * blockDim.x + threadIdx.x) >> 5;
    const int lane = threadIdx.x & 31;
    if (warp >= BDIM) return;
    int cnt = g_plcnt[warp];
    if (cnt > PLCAP) cnt = PLCAP;
    const float base = LSE_C + logf(g_rowsum[warp]);
    float rowsum = 0.f;
    for (int t = lane; t < cnt; t += 32) {
        const float l = g_pl[warp * PLCAP + t];
        const float x = base - l;
        rowsum += (x > 0.f) ? x + log1pf(expf(-x)) : log1pf(expf(x));
    }
#pragma unroll
    for (int o = 16; o > 0; o >>= 1) rowsum += __shfl_xor_sync(0xffffffffu, rowsum, o);
    if (lane == 0 && cnt > 0)
        atomicAdd(&g_acc, (double)(rowsum / (float)cnt));
}

__global__ void finalize_kernel(float* out) {
    out[0] = (float)(g_acc / (double)BDIM);
}

// ---------------------------------------------------------------------------
extern "C" void kernel_launch(void* const* d_in, const int* in_sizes, int n_in,
                              void* d_out, int out_size) {
    const float* E   = nullptr;
    const int*   lab = nullptr;
    for (int i = 0; i < n_in; i++) {
        if (in_sizes[i] == BDIM * DDIM) E   = (const float*)d_in[i];
        else if (in_sizes[i] == BDIM)   lab = (const int*)d_in[i];
    }
    float* out = (float*)d_out;

    cudaFuncSetAttribute(lse_gemm_kernel,
                         cudaFuncAttributeMaxDynamicSharedMemorySize, SMEM_BYTES);

    init_kernel<<<(BDIM + 255) / 256, 256>>>();
    convert_kernel<<<(BDIM * DDIM / 4) / 256, 256>>>(E);
    lse_gemm_kernel<<<TOT_TILES, 256, SMEM_BYTES>>>(lab);
    pair_kernel<<<BDIM / 8, 256>>>();
    finalize_kernel<<<1, 1>>>(out);
}